// round 4
// baseline (speedup 1.0000x reference)
#include <cuda_runtime.h>

#define BATCH 128
#define SEQ   2000
#define EMB   50
#define VOCAB 1000000
#define SPLIT 10
#define CHUNK (SEQ / SPLIT)      // 200 tokens per block
#define WARPS 8
#define THREADS (WARPS * 32)
#define HALF_EMB 25              // 25 float2 per row

// Partial pooled sums, transposed for coalesced finalize reads:
// layout [j in 0..24][sp in 0..SPLIT-1][b in 0..127] of float2.
__device__ float2 g_partial[HALF_EMB * SPLIT * BATCH];

__global__ __launch_bounds__(THREADS) void accum_kernel(
    const int* __restrict__ t32, const float* __restrict__ emb)
{
    const int b     = blockIdx.y;
    const int chunk = blockIdx.x;
    const int warp  = threadIdx.x >> 5;
    const int lane  = threadIdx.x & 31;

    // ---- inline dtype detect (warp 0, 1 parallel load + ballot) ----
    // int64 indices in [-1, 1e6) have every odd 32-bit word == 0 or -1;
    // int32 index data has random indices there -> ballot != full.
    __shared__ int s_is64;
    if (threadIdx.x < 32) {
        const unsigned int hi =
            reinterpret_cast<const unsigned int*>(t32)[2 * lane + 1];
        const bool ok = (hi == 0u) || (hi == 0xFFFFFFFFu);
        const unsigned m = __ballot_sync(0xFFFFFFFFu, ok);
        if (lane == 0) s_is64 = (m == 0xFFFFFFFFu) ? 1 : 0;
    }
    __syncthreads();
    const int stride = s_is64 ? 2 : 1;   // 32-bit-word stride per index

    const int* trow = t32 + ((long long)b * SEQ + (long long)chunk * CHUNK) * stride;

    const bool active = (lane < HALF_EMB);
    const int  foff   = 2 * lane;        // float offset within an embedding row

    float2 a0 = make_float2(0.f, 0.f);
    float2 a1 = make_float2(0.f, 0.f);
    float2 a2 = make_float2(0.f, 0.f);
    float2 a3 = make_float2(0.f, 0.f);

    int s = warp;
    // 4 independent gather streams per lane -> MLP ~4 row-loads in flight.
    for (; s + 3 * WARPS < CHUNK; s += 4 * WARPS) {
        const int v0 = trow[(s)             * stride];
        const int v1 = trow[(s +     WARPS) * stride];
        const int v2 = trow[(s + 2 * WARPS) * stride];
        const int v3 = trow[(s + 3 * WARPS) * stride];
        if (active) {
            if ((unsigned)v0 < (unsigned)VOCAB) {
                const float2 e = *reinterpret_cast<const float2*>(
                    emb + (long long)v0 * EMB + foff);
                a0.x += e.x; a0.y += e.y;
            }
            if ((unsigned)v1 < (unsigned)VOCAB) {
                const float2 e = *reinterpret_cast<const float2*>(
                    emb + (long long)v1 * EMB + foff);
                a1.x += e.x; a1.y += e.y;
            }
            if ((unsigned)v2 < (unsigned)VOCAB) {
                const float2 e = *reinterpret_cast<const float2*>(
                    emb + (long long)v2 * EMB + foff);
                a2.x += e.x; a2.y += e.y;
            }
            if ((unsigned)v3 < (unsigned)VOCAB) {
                const float2 e = *reinterpret_cast<const float2*>(
                    emb + (long long)v3 * EMB + foff);
                a3.x += e.x; a3.y += e.y;
            }
        }
    }
    for (; s < CHUNK; s += WARPS) {
        const int v = trow[s * stride];
        if (active && (unsigned)v < (unsigned)VOCAB) {
            const float2 e = *reinterpret_cast<const float2*>(
                emb + (long long)v * EMB + foff);
            a0.x += e.x; a0.y += e.y;
        }
    }
    a0.x += a1.x + a2.x + a3.x;
    a0.y += a1.y + a2.y + a3.y;

    // Block reduction across the 8 warps.
    __shared__ float2 red[WARPS][HALF_EMB];
    if (active) red[warp][lane] = a0;
    __syncthreads();

    if (threadIdx.x < HALF_EMB) {
        const int j = threadIdx.x;
        float2 sum = red[0][j];
        #pragma unroll
        for (int w = 1; w < WARPS; w++) {
            sum.x += red[w][j].x;
            sum.y += red[w][j].y;
        }
        g_partial[(j * SPLIT + chunk) * BATCH + b] = sum;
    }
}

__global__ __launch_bounds__(128) void finalize_kernel(
    const float* __restrict__ W, const float* __restrict__ bias,
    float* __restrict__ out)
{
    const int b = threadIdx.x;     // one thread per batch row
    if (b >= BATCH) return;

    float o0 = bias[0];
    float o1 = bias[1];
    const float scale = 1.0f / (float)BATCH;   // reference divides by len(t)==BATCH

    #pragma unroll
    for (int j = 0; j < HALF_EMB; j++) {
        float2 p = make_float2(0.f, 0.f);
        #pragma unroll
        for (int sp = 0; sp < SPLIT; sp++) {
            // coalesced across b (adjacent threads -> adjacent float2)
            const float2 q = g_partial[(j * SPLIT + sp) * BATCH + b];
            p.x += q.x; p.y += q.y;
        }
        p.x *= scale; p.y *= scale;
        o0 += p.x * W[2 * j]       + p.y * W[2 * j + 1];
        o1 += p.x * W[EMB + 2 * j] + p.y * W[EMB + 2 * j + 1];
    }
    out[2 * b + 0] = fmaxf(o0, 0.0f);
    out[2 * b + 1] = fmaxf(o1, 0.0f);
}

extern "C" void kernel_launch(void* const* d_in, const int* in_sizes, int n_in,
                              void* d_out, int out_size)
{
    const int*   t32 = (const int*)d_in[0];        // int32 OR int64 [128, 2000]
    const float* emb = (const float*)d_in[1];      // f32 [1e6, 50]
    const float* W   = (const float*)d_in[2];      // f32 [2, 50]
    const float* bia = (const float*)d_in[3];      // f32 [2]
    float*       out = (float*)d_out;              // f32 [128, 2]

    dim3 grid(SPLIT, BATCH);
    accum_kernel<<<grid, THREADS>>>(t32, emb);
    finalize_kernel<<<1, 128>>>(W, bia, out);
}

// round 6
// speedup vs baseline: 1.9848x; 1.9848x over previous
#include <cuda_runtime.h>

#define BATCH 128
#define SEQ   2000
#define EMB   50
#define VOCAB 1000000
#define SPLIT 10
#define CHUNK (SEQ / SPLIT)      // 200 tokens per block
#define WARPS 8
#define THREADS (WARPS * 32)
#define HALF_EMB 25              // 25 float2 per row
#define FPARTS 8                 // finalize j-partitions
#define FTHREADS (FPARTS * BATCH)  // 1024

// Partial pooled sums, [j][sp][b] float2 -> coalesced finalize reads.
__device__ float2 g_partial[HALF_EMB * SPLIT * BATCH];

__global__ __launch_bounds__(THREADS) void accum_kernel(
    const int* __restrict__ t32, const float* __restrict__ emb)
{
    const int b     = blockIdx.y;
    const int chunk = blockIdx.x;
    const int warp  = threadIdx.x >> 5;
    const int lane  = threadIdx.x & 31;

    // ---- inline dtype detect (warp 0: 1 parallel load + ballot) ----
    // int64 indices in [-1, 1e6): every odd 32-bit word is 0 or -1.
    __shared__ int s_is64;
    if (threadIdx.x < 32) {
        const unsigned int hi =
            reinterpret_cast<const unsigned int*>(t32)[2 * lane + 1];
        const bool ok = (hi == 0u) || (hi == 0xFFFFFFFFu);
        const unsigned m = __ballot_sync(0xFFFFFFFFu, ok);
        if (lane == 0) s_is64 = (m == 0xFFFFFFFFu) ? 1 : 0;
    }
    __syncthreads();
    const int stride = s_is64 ? 2 : 1;   // 32-bit-word stride per index

    const int* trow = t32 + ((long long)b * SEQ + (long long)chunk * CHUNK) * stride;

    const bool active = (lane < HALF_EMB);
    const int  foff   = 2 * lane;        // float offset within an embedding row

    float2 a0 = make_float2(0.f, 0.f);
    float2 a1 = make_float2(0.f, 0.f);
    float2 a2 = make_float2(0.f, 0.f);
    float2 a3 = make_float2(0.f, 0.f);

    int s = warp;
    // 4 independent gather streams per lane.
    for (; s + 3 * WARPS < CHUNK; s += 4 * WARPS) {
        const int v0 = trow[(s)             * stride];
        const int v1 = trow[(s +     WARPS) * stride];
        const int v2 = trow[(s + 2 * WARPS) * stride];
        const int v3 = trow[(s + 3 * WARPS) * stride];
        if (active) {
            if ((unsigned)v0 < (unsigned)VOCAB) {
                const float2 e = *reinterpret_cast<const float2*>(
                    emb + (long long)v0 * EMB + foff);
                a0.x += e.x; a0.y += e.y;
            }
            if ((unsigned)v1 < (unsigned)VOCAB) {
                const float2 e = *reinterpret_cast<const float2*>(
                    emb + (long long)v1 * EMB + foff);
                a1.x += e.x; a1.y += e.y;
            }
            if ((unsigned)v2 < (unsigned)VOCAB) {
                const float2 e = *reinterpret_cast<const float2*>(
                    emb + (long long)v2 * EMB + foff);
                a2.x += e.x; a2.y += e.y;
            }
            if ((unsigned)v3 < (unsigned)VOCAB) {
                const float2 e = *reinterpret_cast<const float2*>(
                    emb + (long long)v3 * EMB + foff);
                a3.x += e.x; a3.y += e.y;
            }
        }
    }
    for (; s < CHUNK; s += WARPS) {
        const int v = trow[s * stride];
        if (active && (unsigned)v < (unsigned)VOCAB) {
            const float2 e = *reinterpret_cast<const float2*>(
                emb + (long long)v * EMB + foff);
            a0.x += e.x; a0.y += e.y;
        }
    }
    a0.x += a1.x + a2.x + a3.x;
    a0.y += a1.y + a2.y + a3.y;

    __shared__ float2 red[WARPS][HALF_EMB];
    if (active) red[warp][lane] = a0;
    __syncthreads();

    if (threadIdx.x < HALF_EMB) {
        const int j = threadIdx.x;
        float2 sum = red[0][j];
        #pragma unroll
        for (int w = 1; w < WARPS; w++) {
            sum.x += red[w][j].x;
            sum.y += red[w][j].y;
        }
        g_partial[(j * SPLIT + chunk) * BATCH + b] = sum;
    }
}

// 1 block x 1024 threads: thread = (part, b). Each part covers a strided
// subset of the 25 j-slots; partial dot products reduced in shared.
__global__ __launch_bounds__(FTHREADS) void finalize_kernel(
    const float* __restrict__ W, const float* __restrict__ bias,
    float* __restrict__ out)
{
    const int part = threadIdx.x >> 7;      // 0..7
    const int b    = threadIdx.x & (BATCH - 1);

    float o0 = 0.f, o1 = 0.f;
    for (int j = part; j < HALF_EMB; j += FPARTS) {
        float2 p = make_float2(0.f, 0.f);
        #pragma unroll
        for (int sp = 0; sp < SPLIT; sp++) {
            const float2 q = g_partial[(j * SPLIT + sp) * BATCH + b];
            p.x += q.x; p.y += q.y;
        }
        o0 += p.x * W[2 * j]       + p.y * W[2 * j + 1];
        o1 += p.x * W[EMB + 2 * j] + p.y * W[EMB + 2 * j + 1];
    }

    __shared__ float2 sred[FPARTS][BATCH];
    sred[part][b] = make_float2(o0, o1);
    __syncthreads();

    if (part == 0) {
        float s0 = 0.f, s1 = 0.f;
        #pragma unroll
        for (int p2 = 0; p2 < FPARTS; p2++) {
            s0 += sred[p2][b].x;
            s1 += sred[p2][b].y;
        }
        const float scale = 1.0f / (float)BATCH;  // reference divides by len(t)
        out[2 * b + 0] = fmaxf(bias[0] + scale * s0, 0.0f);
        out[2 * b + 1] = fmaxf(bias[1] + scale * s1, 0.0f);
    }
}

extern "C" void kernel_launch(void* const* d_in, const int* in_sizes, int n_in,
                              void* d_out, int out_size)
{
    const int*   t32 = (const int*)d_in[0];        // int32 OR int64 [128, 2000]
    const float* emb = (const float*)d_in[1];      // f32 [1e6, 50]
    const float* W   = (const float*)d_in[2];      // f32 [2, 50]
    const float* bia = (const float*)d_in[3];      // f32 [2]
    float*       out = (float*)d_out;              // f32 [128, 2]

    dim3 grid(SPLIT, BATCH);
    accum_kernel<<<grid, THREADS>>>(t32, emb);
    finalize_kernel<<<1, FTHREADS>>>(W, bia, out);
}

// round 10
// speedup vs baseline: 2.0429x; 1.0292x over previous
#include <cuda_runtime.h>

#define BATCH 128
#define SEQ   2000
#define EMB   50
#define VOCAB 1000000
#define SPLIT 10
#define CHUNK (SEQ / SPLIT)      // 200 tokens per block
#define WARPS 8
#define THREADS (WARPS * 32)
#define HALF_EMB 25              // 25 float2 per row

// Per-block partial dot products: [sp][b] -> (o0, o1). Only 10 KB total.
__device__ float2 g_dot[SPLIT * BATCH];

__global__ __launch_bounds__(THREADS) void accum_kernel(
    const int* __restrict__ t32, const float* __restrict__ emb,
    const float* __restrict__ W)
{
    const int b     = blockIdx.y;
    const int chunk = blockIdx.x;
    const int warp  = threadIdx.x >> 5;
    const int lane  = threadIdx.x & 31;

    // ---- inline dtype detect (warp 0: 1 parallel load + ballot) ----
    // int64 indices in [-1, 1e6): every odd 32-bit word is 0 or -1.
    __shared__ int s_is64;
    if (threadIdx.x < 32) {
        const unsigned int hi =
            reinterpret_cast<const unsigned int*>(t32)[2 * lane + 1];
        const bool ok = (hi == 0u) || (hi == 0xFFFFFFFFu);
        const unsigned m = __ballot_sync(0xFFFFFFFFu, ok);
        if (lane == 0) s_is64 = (m == 0xFFFFFFFFu) ? 1 : 0;
    }
    __syncthreads();
    const int stride = s_is64 ? 2 : 1;   // 32-bit-word stride per index

    const int* trow = t32 + ((long long)b * SEQ + (long long)chunk * CHUNK) * stride;

    const bool active = (lane < HALF_EMB);
    const int  foff   = 2 * lane;        // float offset within an embedding row

    float2 a0 = make_float2(0.f, 0.f);
    float2 a1 = make_float2(0.f, 0.f);
    float2 a2 = make_float2(0.f, 0.f);
    float2 a3 = make_float2(0.f, 0.f);

    int s = warp;
    // 4 independent gather streams per lane.
    for (; s + 3 * WARPS < CHUNK; s += 4 * WARPS) {
        const int v0 = trow[(s)             * stride];
        const int v1 = trow[(s +     WARPS) * stride];
        const int v2 = trow[(s + 2 * WARPS) * stride];
        const int v3 = trow[(s + 3 * WARPS) * stride];
        if (active) {
            if ((unsigned)v0 < (unsigned)VOCAB) {
                const float2 e = *reinterpret_cast<const float2*>(
                    emb + (long long)v0 * EMB + foff);
                a0.x += e.x; a0.y += e.y;
            }
            if ((unsigned)v1 < (unsigned)VOCAB) {
                const float2 e = *reinterpret_cast<const float2*>(
                    emb + (long long)v1 * EMB + foff);
                a1.x += e.x; a1.y += e.y;
            }
            if ((unsigned)v2 < (unsigned)VOCAB) {
                const float2 e = *reinterpret_cast<const float2*>(
                    emb + (long long)v2 * EMB + foff);
                a2.x += e.x; a2.y += e.y;
            }
            if ((unsigned)v3 < (unsigned)VOCAB) {
                const float2 e = *reinterpret_cast<const float2*>(
                    emb + (long long)v3 * EMB + foff);
                a3.x += e.x; a3.y += e.y;
            }
        }
    }
    for (; s < CHUNK; s += WARPS) {
        const int v = trow[s * stride];
        if (active && (unsigned)v < (unsigned)VOCAB) {
            const float2 e = *reinterpret_cast<const float2*>(
                emb + (long long)v * EMB + foff);
            a0.x += e.x; a0.y += e.y;
        }
    }
    a0.x += a1.x + a2.x + a3.x;
    a0.y += a1.y + a2.y + a3.y;

    // Block reduction across the 8 warps (per embedding-pair slot j = lane).
    __shared__ float2 red[WARPS][HALF_EMB];
    if (active) red[warp][lane] = a0;
    __syncthreads();

    // Warp 0: fold the 25 slots into the 2 output dot products directly.
    if (warp == 0) {
        float c0 = 0.f, c1 = 0.f;
        if (active) {
            const int j = lane;
            const float w00 = __ldg(&W[2 * j]);
            const float w01 = __ldg(&W[2 * j + 1]);
            const float w10 = __ldg(&W[EMB + 2 * j]);
            const float w11 = __ldg(&W[EMB + 2 * j + 1]);
            float2 sum = red[0][j];
            #pragma unroll
            for (int w = 1; w < WARPS; w++) {
                sum.x += red[w][j].x;
                sum.y += red[w][j].y;
            }
            c0 = sum.x * w00 + sum.y * w01;
            c1 = sum.x * w10 + sum.y * w11;
        }
        #pragma unroll
        for (int off = 16; off > 0; off >>= 1) {
            c0 += __shfl_down_sync(0xFFFFFFFFu, c0, off);
            c1 += __shfl_down_sync(0xFFFFFFFFu, c1, off);
        }
        if (lane == 0)
            g_dot[chunk * BATCH + b] = make_float2(c0, c1);
    }
}

// Tiny epilogue: 128 threads, 10 coalesced float2 loads each (10 KB total).
__global__ __launch_bounds__(BATCH) void finalize_kernel(
    const float* __restrict__ bias, float* __restrict__ out)
{
    const int b = threadIdx.x;
    float s0 = 0.f, s1 = 0.f;
    #pragma unroll
    for (int sp = 0; sp < SPLIT; sp++) {
        const float2 q = g_dot[sp * BATCH + b];   // coalesced across b
        s0 += q.x; s1 += q.y;
    }
    const float scale = 1.0f / (float)BATCH;      // reference divides by len(t)
    out[2 * b + 0] = fmaxf(bias[0] + scale * s0, 0.0f);
    out[2 * b + 1] = fmaxf(bias[1] + scale * s1, 0.0f);
}

extern "C" void kernel_launch(void* const* d_in, const int* in_sizes, int n_in,
                              void* d_out, int out_size)
{
    const int*   t32 = (const int*)d_in[0];        // int32 OR int64 [128, 2000]
    const float* emb = (const float*)d_in[1];      // f32 [1e6, 50]
    const float* W   = (const float*)d_in[2];      // f32 [2, 50]
    const float* bia = (const float*)d_in[3];      // f32 [2]
    float*       out = (float*)d_out;              // f32 [128, 2]

    dim3 grid(SPLIT, BATCH);
    accum_kernel<<<grid, THREADS>>>(t32, emb, W);
    finalize_kernel<<<1, BATCH>>>(bia, out);
}